// round 16
// baseline (speedup 1.0000x reference)
#include <cuda_runtime.h>
#include <cuda_bf16.h>

#define N 512
#define D 256
#define KSPLIT 8

// Scratch (device globals — no allocation allowed)
__device__ float g_k[N * N];
__device__ float g_v[N * N];
__device__ float g_sp[KSPLIT][N * N];   // split-K partials of q@k
__device__ float g_op[KSPLIT][N * N];   // split-K partials of s@v

// bf16 hi/lo split operands for the tensor-core GEMMs
__device__ __align__(16) __nv_bfloat16 qh[N * N], ql[N * N];    // q  [m][k]
__device__ __align__(16) __nv_bfloat16 kht[N * N], klt[N * N];  // k^T [n][k]
__device__ __align__(16) __nv_bfloat16 sh_[N * N], sl_[N * N];  // s  [m][k]
__device__ __align__(16) __nv_bfloat16 vht[N * N], vlt[N * N];  // v^T [n][k]

#define PROJ_BLOCKS 1184   // 148 * 8 (persistent single wave)

__device__ __forceinline__ float dot4(float4 a, float4 b) {
    return a.x * b.x + a.y * b.y + a.z * b.z + a.w * b.w;
}

// m16n8k16 bf16 MMA, fp32 accumulate (row-major A, col-major B)
__device__ __forceinline__ void mma16816(float* c, const unsigned* a,
                                         unsigned b0, unsigned b1) {
    asm volatile(
        "mma.sync.aligned.m16n8k16.row.col.f32.bf16.bf16.f32 "
        "{%0,%1,%2,%3}, {%4,%5,%6,%7}, {%8,%9}, {%0,%1,%2,%3};"
        : "+f"(c[0]), "+f"(c[1]), "+f"(c[2]), "+f"(c[3])
        : "r"(a[0]), "r"(a[1]), "r"(a[2]), "r"(a[3]), "r"(b0), "r"(b1));
}

// ldmatrix m8n8.x4 (non-transposed), per-lane row address
__device__ __forceinline__ void ldsm4(unsigned* r, const __nv_bfloat16* p) {
    unsigned addr = (unsigned)__cvta_generic_to_shared(p);
    asm volatile(
        "ldmatrix.sync.aligned.m8n8.x4.shared.b16 {%0,%1,%2,%3}, [%4];"
        : "=r"(r[0]), "=r"(r[1]), "=r"(r[2]), "=r"(r[3]) : "r"(addr));
}

// ---------------------------------------------------------------------------
// Kernel 1: fused rank-1 projections (LTS-capped config, 6.8 TB/s).
// q is written directly as bf16 hi/lo split; k,v stay fp32 for transposing.
// ---------------------------------------------------------------------------
__global__ void __launch_bounds__(256) proj_kernel(
    const float* __restrict__ xq, const float* __restrict__ xk,
    const float* __restrict__ xv, const float* __restrict__ WQ,
    const float* __restrict__ WK, const float* __restrict__ WV)
{
    __shared__ float sW[3][D];
    int tid = threadIdx.x;
    sW[0][tid] = WQ[tid];
    sW[1][tid] = WK[tid];
    sW[2][tid] = WV[tid];
    __syncthreads();

    const int warp = tid >> 5;
    const int lane = tid & 31;
    const long long stride = (long long)PROJ_BLOCKS * 8;
    const long long total = 3LL * N * N;

    for (long long row = (long long)blockIdx.x * 8 + warp; row < total; row += stride) {
        int t = (int)(row >> 18);
        int r = (int)(row & (N * N - 1));

        const float* x = (t == 0) ? xq : (t == 1) ? xk : xv;
        const float4* xr = reinterpret_cast<const float4*>(x + (size_t)r * D);
        const float4* w4 = reinterpret_cast<const float4*>(sW[t]);

        float4 a0 = __ldcs(&xr[lane]);
        float4 a1 = __ldcs(&xr[lane + 32]);
        float4 b0 = w4[lane];
        float4 b1 = w4[lane + 32];

        float acc = dot4(a0, b0) + dot4(a1, b1);

#pragma unroll
        for (int o = 16; o > 0; o >>= 1)
            acc += __shfl_xor_sync(0xffffffffu, acc, o);

        if (lane == 0) {
            if (t == 0) {
                __nv_bfloat16 h = __float2bfloat16(acc);
                qh[r] = h;
                ql[r] = __float2bfloat16(acc - __bfloat162float(h));
            } else if (t == 1) {
                g_k[r] = acc;
            } else {
                g_v[r] = acc;
            }
        }
    }
}

// ---------------------------------------------------------------------------
// Kernel 2: transpose + bf16 hi/lo split. out[j][i] = split(in[i][j]).
// mode 0: g_k -> kht/klt ; mode 1: g_v -> vht/vlt. grid (16,16), 256 thr.
// ---------------------------------------------------------------------------
__global__ void __launch_bounds__(256) tsplit_kernel(int mode)
{
    const float* __restrict__ in = (mode == 0) ? g_k : g_v;
    __nv_bfloat16* __restrict__ oh = (mode == 0) ? kht : vht;
    __nv_bfloat16* __restrict__ ol = (mode == 0) ? klt : vlt;

    __shared__ float t[32][33];
    const int bi = blockIdx.x * 32;
    const int bj = blockIdx.y * 32;
    const int tx = threadIdx.x & 31;
    const int ty = threadIdx.x >> 5;

#pragma unroll
    for (int r = 0; r < 4; r++)
        t[ty + r * 8][tx] = in[(size_t)(bi + ty + r * 8) * N + bj + tx];
    __syncthreads();

#pragma unroll
    for (int r = 0; r < 4; r++) {
        float v = t[tx][ty + r * 8];
        __nv_bfloat16 h = __float2bfloat16(v);
        __nv_bfloat16 l = __float2bfloat16(v - __bfloat162float(h));
        size_t o = (size_t)(bj + ty + r * 8) * N + bi + tx;
        oh[o] = h;
        ol[o] = l;
    }
}

// ---------------------------------------------------------------------------
// Kernel 3/5: tensor-core GEMM partials, 3xBF16 error-compensated.
// ldmatrix fragment loads + split accumulator chains.
// Block tile 64m x 64n; 8 warps (4m x 2n); warp tile 16m x 32n.
// grid (8 n, 8 m, KSPLIT) = 512 blocks.
// ---------------------------------------------------------------------------
__global__ void __launch_bounds__(256, 2) mma_gemm_kernel(int mode)
{
    const __nv_bfloat16* __restrict__ Ah = (mode == 0) ? qh : sh_;
    const __nv_bfloat16* __restrict__ Al = (mode == 0) ? ql : sl_;
    const __nv_bfloat16* __restrict__ Bh = (mode == 0) ? kht : vht;
    const __nv_bfloat16* __restrict__ Bl = (mode == 0) ? klt : vlt;
    float* __restrict__ C = (mode == 0) ? g_sp[blockIdx.z] : g_op[blockIdx.z];

    // +8 bf16 pad: 144B row stride = 9 x 16B -> 8 LDSM rows hit distinct banks
    __shared__ __align__(16) __nv_bfloat16 sAh[64][72], sAl[64][72];
    __shared__ __align__(16) __nv_bfloat16 sBh[64][72], sBl[64][72];

    const int bx = blockIdx.x * 64;   // n
    const int by = blockIdx.y * 64;   // m
    const int kb = blockIdx.z * 64;   // K slice

    const int tid = threadIdx.x;
    const int lane = tid & 31;
    const int warp = tid >> 5;
    const int wm = warp >> 1;         // m offset wm*16
    const int wn = warp & 1;          // n offset wn*32
    const int gid = lane >> 2;
    const int tig = lane & 3;

    // Load 4 tiles of 64x64 bf16 (each 512 uint4; 2 per thread)
#pragma unroll
    for (int i = 0; i < 2; i++) {
        int idx = tid + i * 256;
        int r = idx >> 3;
        int c = (idx & 7) * 8;
        *(uint4*)&sAh[r][c] = *(const uint4*)&Ah[(size_t)(by + r) * N + kb + c];
        *(uint4*)&sAl[r][c] = *(const uint4*)&Al[(size_t)(by + r) * N + kb + c];
        *(uint4*)&sBh[r][c] = *(const uint4*)&Bh[(size_t)(bx + r) * N + kb + c];
        *(uint4*)&sBl[r][c] = *(const uint4*)&Bl[(size_t)(bx + r) * N + kb + c];
    }
    __syncthreads();

    // LDSM per-lane row indices
    // A tiles: t0=(m0,k0) t1=(m8,k0) t2=(m0,k8) t3=(m8,k8)
    const int a_row = wm * 16 + ((lane >> 3) & 1) * 8 + (lane & 7);
    const int a_koff = (lane >> 4) * 8;
    // B tiles: t = ni 0..3 at fixed k-half
    const int b_row = wn * 32 + (lane >> 3) * 8 + (lane & 7);

    float accH[4][4] = {};   // hi*hi
    float accC[4][4] = {};   // hi*lo + lo*hi

#pragma unroll
    for (int ks = 0; ks < 4; ks++) {
        const int k0 = ks * 16;

        unsigned aH[4], aL[4];
        ldsm4(aH, &sAh[a_row][k0 + a_koff]);
        ldsm4(aL, &sAl[a_row][k0 + a_koff]);

        unsigned bh0[4], bh1[4], bl0[4], bl1[4];
        ldsm4(bh0, &sBh[b_row][k0]);
        ldsm4(bh1, &sBh[b_row][k0 + 8]);
        ldsm4(bl0, &sBl[b_row][k0]);
        ldsm4(bl1, &sBl[b_row][k0 + 8]);

#pragma unroll
        for (int ni = 0; ni < 4; ni++)
            mma16816(accH[ni], aH, bh0[ni], bh1[ni]);
#pragma unroll
        for (int ni = 0; ni < 4; ni++)
            mma16816(accC[ni], aH, bl0[ni], bl1[ni]);
#pragma unroll
        for (int ni = 0; ni < 4; ni++)
            mma16816(accC[ni], aL, bh0[ni], bh1[ni]);
    }

    // Epilogue: c0,c1 row=gid col=tig*2,+1 ; c2,c3 row+8
#pragma unroll
    for (int ni = 0; ni < 4; ni++) {
        int row = by + wm * 16 + gid;
        int col = bx + wn * 32 + ni * 8 + tig * 2;
        *(float2*)&C[(size_t)row * N + col] =
            make_float2(accH[ni][0] + accC[ni][0], accH[ni][1] + accC[ni][1]);
        *(float2*)&C[(size_t)(row + 8) * N + col] =
            make_float2(accH[ni][2] + accC[ni][2], accH[ni][3] + accC[ni][3]);
    }
}

// ---------------------------------------------------------------------------
// Kernel 4: sum KSPLIT s-partials + row softmax -> sh_/sl_ (bf16 split).
// ---------------------------------------------------------------------------
__global__ void __launch_bounds__(256) softmax_kernel()
{
    __shared__ float smax[2][4];
    __shared__ float ssum[2][4];

    const int tid = threadIdx.x;
    const int half = tid >> 7;
    const int t = tid & 127;
    const int warp = (tid >> 5) & 3;
    const int lane = tid & 31;
    const int row = blockIdx.x * 2 + half;
    const size_t off = (size_t)row * N + t * 4;

    float4 a = make_float4(0.f, 0.f, 0.f, 0.f);
#pragma unroll
    for (int z = 0; z < KSPLIT; z++) {
        float4 p = *(const float4*)&g_sp[z][off];
        a.x += p.x; a.y += p.y; a.z += p.z; a.w += p.w;
    }

    float mx = fmaxf(fmaxf(a.x, a.y), fmaxf(a.z, a.w));
#pragma unroll
    for (int o = 16; o > 0; o >>= 1)
        mx = fmaxf(mx, __shfl_xor_sync(0xffffffffu, mx, o));
    if (lane == 0) smax[half][warp] = mx;
    __syncthreads();
    mx = fmaxf(fmaxf(smax[half][0], smax[half][1]),
               fmaxf(smax[half][2], smax[half][3]));

    float4 e;
    e.x = __expf(a.x - mx);
    e.y = __expf(a.y - mx);
    e.z = __expf(a.z - mx);
    e.w = __expf(a.w - mx);

    float s = e.x + e.y + e.z + e.w;
#pragma unroll
    for (int o = 16; o > 0; o >>= 1)
        s += __shfl_xor_sync(0xffffffffu, s, o);
    if (lane == 0) ssum[half][warp] = s;
    __syncthreads();
    float inv = 1.0f / (ssum[half][0] + ssum[half][1] + ssum[half][2] + ssum[half][3]);

    float v[4] = { e.x * inv, e.y * inv, e.z * inv, e.w * inv };
#pragma unroll
    for (int j = 0; j < 4; j++) {
        __nv_bfloat16 h = __float2bfloat16(v[j]);
        sh_[off + j] = h;
        sl_[off + j] = __float2bfloat16(v[j] - __bfloat162float(h));
    }
}

// ---------------------------------------------------------------------------
// Kernel 6: sum KSPLIT out-partials -> d_out.
// ---------------------------------------------------------------------------
__global__ void __launch_bounds__(256) reduce_out_kernel(float* __restrict__ out)
{
    int i = blockIdx.x * 256 + threadIdx.x;
    float4 r = ((const float4*)g_op[0])[i];
#pragma unroll
    for (int z = 1; z < KSPLIT; z++) {
        float4 s = ((const float4*)g_op[z])[i];
        r.x += s.x; r.y += s.y; r.z += s.z; r.w += s.w;
    }
    ((float4*)out)[i] = r;
}

// ---------------------------------------------------------------------------
extern "C" void kernel_launch(void* const* d_in, const int* in_sizes, int n_in,
                              void* d_out, int out_size)
{
    const float* xq = (const float*)d_in[0];
    const float* xk = (const float*)d_in[1];
    const float* xv = (const float*)d_in[2];
    const float* WQ = (const float*)d_in[3];
    const float* WK = (const float*)d_in[4];
    const float* WV = (const float*)d_in[5];
    float* out = (float*)d_out;

    // 1) projections (q emitted as bf16 hi/lo; k,v fp32)
    proj_kernel<<<PROJ_BLOCKS, 256>>>(xq, xk, xv, WQ, WK, WV);

    // 2) transpose+split k and v for the tensor GEMM B operands
    dim3 tg(16, 16);
    tsplit_kernel<<<tg, 256>>>(0);
    tsplit_kernel<<<tg, 256>>>(1);

    // 3) y partials = q @ k (3xBF16 tensor cores, split-K)
    dim3 gg(N / 64, N / 64, KSPLIT);   // (8,8,8) = 512 blocks
    mma_gemm_kernel<<<gg, 256>>>(0);

    // 4) softmax (emits s as bf16 hi/lo)
    softmax_kernel<<<N / 2, 256>>>();

    // 5) out partials = s @ v
    mma_gemm_kernel<<<gg, 256>>>(1);

    // 6) sum partials -> out
    reduce_out_kernel<<<(N * N / 4) / 256, 256>>>(out);
}

// round 17
// speedup vs baseline: 1.0147x; 1.0147x over previous
#include <cuda_runtime.h>
#include <cuda_bf16.h>

#define N 512
#define D 256
#define KSPLIT 4

// Scratch (device globals — no allocation allowed)
__device__ float g_k[N * N];
__device__ float g_v[N * N];
__device__ float g_sp[KSPLIT][N * N];   // split-K partials of q@k
__device__ float g_op[KSPLIT][N * N];   // split-K partials of s@v

// bf16 hi/lo split operands for the tensor-core GEMMs
__device__ __align__(16) __nv_bfloat16 qh[N * N], ql[N * N];    // q  [m][k]
__device__ __align__(16) __nv_bfloat16 kht[N * N], klt[N * N];  // k^T [n][k]
__device__ __align__(16) __nv_bfloat16 sh_[N * N], sl_[N * N];  // s  [m][k]
__device__ __align__(16) __nv_bfloat16 vht[N * N], vlt[N * N];  // v^T [n][k]

#define PROJ_BLOCKS 1184   // 148 * 8 (persistent single wave)

__device__ __forceinline__ float dot4(float4 a, float4 b) {
    return a.x * b.x + a.y * b.y + a.z * b.z + a.w * b.w;
}

// m16n8k16 bf16 MMA, fp32 accumulate (row-major A, col-major B)
__device__ __forceinline__ void mma16816(float* c, const unsigned* a,
                                         unsigned b0, unsigned b1) {
    asm volatile(
        "mma.sync.aligned.m16n8k16.row.col.f32.bf16.bf16.f32 "
        "{%0,%1,%2,%3}, {%4,%5,%6,%7}, {%8,%9}, {%0,%1,%2,%3};"
        : "+f"(c[0]), "+f"(c[1]), "+f"(c[2]), "+f"(c[3])
        : "r"(a[0]), "r"(a[1]), "r"(a[2]), "r"(a[3]), "r"(b0), "r"(b1));
}

// ---------------------------------------------------------------------------
// Kernel 1: fused rank-1 projections (LTS-capped config, 6.8 TB/s).
// q is written directly as bf16 hi/lo split; k,v stay fp32 for transposing.
// ---------------------------------------------------------------------------
__global__ void __launch_bounds__(256) proj_kernel(
    const float* __restrict__ xq, const float* __restrict__ xk,
    const float* __restrict__ xv, const float* __restrict__ WQ,
    const float* __restrict__ WK, const float* __restrict__ WV)
{
    __shared__ float sW[3][D];
    int tid = threadIdx.x;
    sW[0][tid] = WQ[tid];
    sW[1][tid] = WK[tid];
    sW[2][tid] = WV[tid];
    __syncthreads();

    const int warp = tid >> 5;
    const int lane = tid & 31;
    const long long stride = (long long)PROJ_BLOCKS * 8;
    const long long total = 3LL * N * N;

    for (long long row = (long long)blockIdx.x * 8 + warp; row < total; row += stride) {
        int t = (int)(row >> 18);
        int r = (int)(row & (N * N - 1));

        const float* x = (t == 0) ? xq : (t == 1) ? xk : xv;
        const float4* xr = reinterpret_cast<const float4*>(x + (size_t)r * D);
        const float4* w4 = reinterpret_cast<const float4*>(sW[t]);

        float4 a0 = __ldcs(&xr[lane]);
        float4 a1 = __ldcs(&xr[lane + 32]);
        float4 b0 = w4[lane];
        float4 b1 = w4[lane + 32];

        float acc = dot4(a0, b0) + dot4(a1, b1);

#pragma unroll
        for (int o = 16; o > 0; o >>= 1)
            acc += __shfl_xor_sync(0xffffffffu, acc, o);

        if (lane == 0) {
            if (t == 0) {
                __nv_bfloat16 h = __float2bfloat16(acc);
                qh[r] = h;
                ql[r] = __float2bfloat16(acc - __bfloat162float(h));
            } else if (t == 1) {
                g_k[r] = acc;
            } else {
                g_v[r] = acc;
            }
        }
    }
}

// ---------------------------------------------------------------------------
// Kernel 2: transpose + bf16 hi/lo split. out[j][i] = split(in[i][j]).
// mode 0: g_k -> kht/klt ; mode 1: g_v -> vht/vlt. grid (16,16), 256 thr.
// ---------------------------------------------------------------------------
__global__ void __launch_bounds__(256) tsplit_kernel(int mode)
{
    const float* __restrict__ in = (mode == 0) ? g_k : g_v;
    __nv_bfloat16* __restrict__ oh = (mode == 0) ? kht : vht;
    __nv_bfloat16* __restrict__ ol = (mode == 0) ? klt : vlt;

    __shared__ float t[32][33];
    const int bi = blockIdx.x * 32;
    const int bj = blockIdx.y * 32;
    const int tx = threadIdx.x & 31;
    const int ty = threadIdx.x >> 5;

#pragma unroll
    for (int r = 0; r < 4; r++)
        t[ty + r * 8][tx] = in[(size_t)(bi + ty + r * 8) * N + bj + tx];
    __syncthreads();

#pragma unroll
    for (int r = 0; r < 4; r++) {
        float v = t[tx][ty + r * 8];
        __nv_bfloat16 h = __float2bfloat16(v);
        __nv_bfloat16 l = __float2bfloat16(v - __bfloat162float(h));
        size_t o = (size_t)(bj + ty + r * 8) * N + bi + tx;
        oh[o] = h;
        ol[o] = l;
    }
}

// ---------------------------------------------------------------------------
// Kernel 3/5: tensor-core GEMM partials, 3xBF16 error-compensated.
// R15 scalar fragment loads (measured best). Block tile 64m x 64n;
// 8 warps (4m x 2n); K slice = 128 processed as 2 chunks of 64.
// grid (8 n, 8 m, KSPLIT=4) = 256 blocks (~1 wave).
// ---------------------------------------------------------------------------
__global__ void __launch_bounds__(256, 2) mma_gemm_kernel(int mode)
{
    const __nv_bfloat16* __restrict__ Ah = (mode == 0) ? qh : sh_;
    const __nv_bfloat16* __restrict__ Al = (mode == 0) ? ql : sl_;
    const __nv_bfloat16* __restrict__ Bh = (mode == 0) ? kht : vht;
    const __nv_bfloat16* __restrict__ Bl = (mode == 0) ? klt : vlt;
    float* __restrict__ C = (mode == 0) ? g_sp[blockIdx.z] : g_op[blockIdx.z];

    // +8 bf16 pad: 144B row stride (16B-aligned, conflict-spread)
    __shared__ __align__(16) __nv_bfloat16 sAh[64][72], sAl[64][72];
    __shared__ __align__(16) __nv_bfloat16 sBh[64][72], sBl[64][72];

    const int bx = blockIdx.x * 64;            // n
    const int by = blockIdx.y * 64;            // m
    const int kslice = blockIdx.z * (N / KSPLIT);  // 128-wide K slice

    const int tid = threadIdx.x;
    const int lane = tid & 31;
    const int warp = tid >> 5;
    const int wm = warp >> 1;
    const int wn = warp & 1;
    const int gid = lane >> 2;
    const int tig = lane & 3;

    float accH[4][4] = {};   // hi*hi
    float accC[4][4] = {};   // hi*lo + lo*hi

    for (int kc = 0; kc < N / KSPLIT; kc += 64) {
        const int kb = kslice + kc;

        // Load 4 tiles of 64x64 bf16 (each 512 uint4; 2 per thread)
#pragma unroll
        for (int i = 0; i < 2; i++) {
            int idx = tid + i * 256;
            int r = idx >> 3;
            int c = (idx & 7) * 8;
            *(uint4*)&sAh[r][c] = *(const uint4*)&Ah[(size_t)(by + r) * N + kb + c];
            *(uint4*)&sAl[r][c] = *(const uint4*)&Al[(size_t)(by + r) * N + kb + c];
            *(uint4*)&sBh[r][c] = *(const uint4*)&Bh[(size_t)(bx + r) * N + kb + c];
            *(uint4*)&sBl[r][c] = *(const uint4*)&Bl[(size_t)(bx + r) * N + kb + c];
        }
        __syncthreads();

#pragma unroll
        for (int ks = 0; ks < 4; ks++) {
            const int k0 = ks * 16;

            // A fragments (m16k16): scalar loads (measured best layout)
            unsigned aH[4], aL[4];
            {
                int ar = wm * 16 + gid;
                int ac = k0 + tig * 2;
                aH[0] = *(const unsigned*)&sAh[ar][ac];
                aH[1] = *(const unsigned*)&sAh[ar + 8][ac];
                aH[2] = *(const unsigned*)&sAh[ar][ac + 8];
                aH[3] = *(const unsigned*)&sAh[ar + 8][ac + 8];
                aL[0] = *(const unsigned*)&sAl[ar][ac];
                aL[1] = *(const unsigned*)&sAl[ar + 8][ac];
                aL[2] = *(const unsigned*)&sAl[ar][ac + 8];
                aL[3] = *(const unsigned*)&sAl[ar + 8][ac + 8];
            }

#pragma unroll
            for (int ni = 0; ni < 4; ni++) {
                int br = wn * 32 + ni * 8 + gid;
                int bc = k0 + tig * 2;
                unsigned bh0 = *(const unsigned*)&sBh[br][bc];
                unsigned bh1 = *(const unsigned*)&sBh[br][bc + 8];
                unsigned bl0 = *(const unsigned*)&sBl[br][bc];
                unsigned bl1 = *(const unsigned*)&sBl[br][bc + 8];

                mma16816(accH[ni], aH, bh0, bh1);   // hi*hi
                mma16816(accC[ni], aH, bl0, bl1);   // hi*lo
                mma16816(accC[ni], aL, bh0, bh1);   // lo*hi
            }
        }
        __syncthreads();
    }

    // Epilogue: c0,c1 row=gid col=tig*2,+1 ; c2,c3 row+8
#pragma unroll
    for (int ni = 0; ni < 4; ni++) {
        int row = by + wm * 16 + gid;
        int col = bx + wn * 32 + ni * 8 + tig * 2;
        *(float2*)&C[(size_t)row * N + col] =
            make_float2(accH[ni][0] + accC[ni][0], accH[ni][1] + accC[ni][1]);
        *(float2*)&C[(size_t)(row + 8) * N + col] =
            make_float2(accH[ni][2] + accC[ni][2], accH[ni][3] + accC[ni][3]);
    }
}

// ---------------------------------------------------------------------------
// Kernel 4: sum KSPLIT s-partials + row softmax -> sh_/sl_ (bf16 split).
// ---------------------------------------------------------------------------
__global__ void __launch_bounds__(256) softmax_kernel()
{
    __shared__ float smax[2][4];
    __shared__ float ssum[2][4];

    const int tid = threadIdx.x;
    const int half = tid >> 7;
    const int t = tid & 127;
    const int warp = (tid >> 5) & 3;
    const int lane = tid & 31;
    const int row = blockIdx.x * 2 + half;
    const size_t off = (size_t)row * N + t * 4;

    float4 a = make_float4(0.f, 0.f, 0.f, 0.f);
#pragma unroll
    for (int z = 0; z < KSPLIT; z++) {
        float4 p = *(const float4*)&g_sp[z][off];
        a.x += p.x; a.y += p.y; a.z += p.z; a.w += p.w;
    }

    float mx = fmaxf(fmaxf(a.x, a.y), fmaxf(a.z, a.w));
#pragma unroll
    for (int o = 16; o > 0; o >>= 1)
        mx = fmaxf(mx, __shfl_xor_sync(0xffffffffu, mx, o));
    if (lane == 0) smax[half][warp] = mx;
    __syncthreads();
    mx = fmaxf(fmaxf(smax[half][0], smax[half][1]),
               fmaxf(smax[half][2], smax[half][3]));

    float4 e;
    e.x = __expf(a.x - mx);
    e.y = __expf(a.y - mx);
    e.z = __expf(a.z - mx);
    e.w = __expf(a.w - mx);

    float s = e.x + e.y + e.z + e.w;
#pragma unroll
    for (int o = 16; o > 0; o >>= 1)
        s += __shfl_xor_sync(0xffffffffu, s, o);
    if (lane == 0) ssum[half][warp] = s;
    __syncthreads();
    float inv = 1.0f / (ssum[half][0] + ssum[half][1] + ssum[half][2] + ssum[half][3]);

    float v[4] = { e.x * inv, e.y * inv, e.z * inv, e.w * inv };
#pragma unroll
    for (int j = 0; j < 4; j++) {
        __nv_bfloat16 h = __float2bfloat16(v[j]);
        sh_[off + j] = h;
        sl_[off + j] = __float2bfloat16(v[j] - __bfloat162float(h));
    }
}

// ---------------------------------------------------------------------------
// Kernel 6: sum KSPLIT out-partials -> d_out.
// ---------------------------------------------------------------------------
__global__ void __launch_bounds__(256) reduce_out_kernel(float* __restrict__ out)
{
    int i = blockIdx.x * 256 + threadIdx.x;
    float4 r = ((const float4*)g_op[0])[i];
#pragma unroll
    for (int z = 1; z < KSPLIT; z++) {
        float4 s = ((const float4*)g_op[z])[i];
        r.x += s.x; r.y += s.y; r.z += s.z; r.w += s.w;
    }
    ((float4*)out)[i] = r;
}

// ---------------------------------------------------------------------------
extern "C" void kernel_launch(void* const* d_in, const int* in_sizes, int n_in,
                              void* d_out, int out_size)
{
    const float* xq = (const float*)d_in[0];
    const float* xk = (const float*)d_in[1];
    const float* xv = (const float*)d_in[2];
    const float* WQ = (const float*)d_in[3];
    const float* WK = (const float*)d_in[4];
    const float* WV = (const float*)d_in[5];
    float* out = (float*)d_out;

    // 1) projections (q emitted as bf16 hi/lo; k,v fp32)
    proj_kernel<<<PROJ_BLOCKS, 256>>>(xq, xk, xv, WQ, WK, WV);

    // 2) transpose+split k and v for the tensor GEMM B operands
    dim3 tg(16, 16);
    tsplit_kernel<<<tg, 256>>>(0);
    tsplit_kernel<<<tg, 256>>>(1);

    // 3) y partials = q @ k (3xBF16 tensor cores, split-K=4)
    dim3 gg(N / 64, N / 64, KSPLIT);   // (8,8,4) = 256 blocks
    mma_gemm_kernel<<<gg, 256>>>(0);

    // 4) softmax (emits s as bf16 hi/lo)
    softmax_kernel<<<N / 2, 256>>>();

    // 5) out partials = s @ v
    mma_gemm_kernel<<<gg, 256>>>(1);

    // 6) sum partials -> out
    reduce_out_kernel<<<(N * N / 4) / 256, 256>>>(out);
}